// round 3
// baseline (speedup 1.0000x reference)
#include <cuda_runtime.h>
#include <math.h>

#define H   128
#define GG  20
#define KNN 32
#define MAXN 24000
#define MAXE (MAXN*KNN)

// ---------------- scratch (static __device__, no allocation) ----------------
__device__ __align__(16) float g_pos[MAXN*3];
__device__ __align__(16) float g_h  [MAXN*H];
__device__ __align__(16) float g_A  [MAXN*H];   // h @ W1i + b1   (dst part)
__device__ __align__(16) float g_B  [MAXN*H];   // h @ W1j        (src part)
__device__ __align__(16) float g_mi [MAXN*H];
__device__ int   g_nbr[MAXE];
__device__ float g_attr[(size_t)MAXE*GG];
__device__ float g_pre[16*H];

// ---------------- K1: embeddings + composed (sorted) layout ----------------
__global__ void embed_kernel(const float* __restrict__ ppos, const float* __restrict__ pfeat,
                             const float* __restrict__ lpos, const float* __restrict__ lfeat,
                             const float* __restrict__ pw, const float* __restrict__ pb,
                             const float* __restrict__ lw, const float* __restrict__ lb,
                             int n_prot, int n_lig, int n, int Fp, int Fl)
{
    __shared__ float sf[32];
    int i = blockIdx.x, t = threadIdx.x;
    int b = i / n, j = i - b * n;
    const float *feat, *w, *bias, *pos; int F;
    if (j < n_prot) { int r = b*n_prot + j;            feat = pfeat + (size_t)r*Fp; w = pw; bias = pb; pos = ppos + (size_t)r*3; F = Fp; }
    else            { int r = b*n_lig  + (j - n_prot); feat = lfeat + (size_t)r*Fl; w = lw; bias = lb; pos = lpos + (size_t)r*3; F = Fl; }
    if (t < F) sf[t] = feat[t];
    __syncthreads();
    float acc = bias[t];
    for (int f = 0; f < F; ++f) acc += sf[f] * w[f*H + t];
    g_h[(size_t)i*H + t] = acc;
    if (t < 3) g_pos[i*3 + t] = pos[t];
}

// ---------------- K2: brute-force kNN (stable tie-break like jax top_k) -----
__global__ void knn_kernel(int n)
{
    extern __shared__ float spos[];
    int b = blockIdx.y, tid = threadIdx.x;
    const float* gp = g_pos + (size_t)b*n*3;
    for (int i = tid; i < n*3; i += blockDim.x) spos[i] = gp[i];
    __syncthreads();
    int c = blockIdx.x*blockDim.x + tid;
    if (c >= n) return;
    float cx = spos[c*3], cy = spos[c*3+1], cz = spos[c*3+2];
    float bd[KNN]; int bi[KNN];
#pragma unroll
    for (int s = 0; s < KNN; ++s) { bd[s] = 3.402823466e38f; bi[s] = 0x7fffffff; }
    float wd = 3.402823466e38f; int wi = 0x7fffffff; int ws = 0;
    for (int j = 0; j < n; ++j) {
        if (j == c) continue;
        float dx = cx - spos[j*3], dy = cy - spos[j*3+1], dz = cz - spos[j*3+2];
        float d2 = dx*dx + dy*dy + dz*dz;
        if (d2 < wd || (d2 == wd && j < wi)) {
            bd[ws] = d2; bi[ws] = j;
            wd = bd[0]; wi = bi[0]; ws = 0;
#pragma unroll
            for (int s = 1; s < KNN; ++s)
                if (bd[s] > wd || (bd[s] == wd && bi[s] > wi)) { wd = bd[s]; wi = bi[s]; ws = s; }
        }
    }
    size_t base = ((size_t)(b*n + c))*KNN;
#pragma unroll
    for (int s = 0; s < KNN; ++s) g_nbr[base + s] = b*n + bi[s];
}

// ---------------- K3: Gaussian smearing + zero g_pre ------------------------
__global__ void attr_kernel(int E, float step, float coeff)
{
    int e = blockIdx.x*blockDim.x + threadIdx.x;
    if (e >= E) return;
    if (e < 16*H) g_pre[e] = 0.f;
    int dst = e >> 5;
    int src = g_nbr[e];
    float dx = g_pos[dst*3]   - g_pos[src*3];
    float dy = g_pos[dst*3+1] - g_pos[src*3+1];
    float dz = g_pos[dst*3+2] - g_pos[src*3+2];
    float d = sqrtf(dx*dx + dy*dy + dz*dz);
    size_t o = (size_t)e*GG;
#pragma unroll
    for (int g = 0; g < GG; ++g) {
        float t = d - g*step;
        g_attr[o + g] = expf(coeff*t*t);
    }
}

// ---------------- K4: A = h@W1i + b1, B = h@W1j  (one fused k-loop) ---------
__global__ void __launch_bounds__(256) ab_kernel(const float* __restrict__ edge_w1,
                                                 const float* __restrict__ edge_b1, int l)
{
    __shared__ float sHt[128*34];
    int tid = threadIdx.x;
    int nb = blockIdx.x*32;
    for (int i = tid; i < 32*H; i += 256) { int nn = i>>7, k = i&127; sHt[k*34+nn] = g_h[(size_t)(nb+nn)*H + k]; }
    __syncthreads();
    int cg = tid & 15, ng = tid >> 4, col = cg*8;
    const float4* WA = (const float4*)(edge_w1 + (size_t)l*276*H + GG*H);
    const float4* WB = (const float4*)(edge_w1 + (size_t)l*276*H + (GG+H)*H);
    float accA[2][8], accB[2][8];
#pragma unroll
    for (int c = 0; c < 8; ++c) {
        float b0 = edge_b1[l*H + col + c];
        accA[0][c] = b0; accA[1][c] = b0; accB[0][c] = 0.f; accB[1][c] = 0.f;
    }
#pragma unroll 2
    for (int k = 0; k < H; ++k) {
        float2 a  = *(const float2*)(sHt + k*34 + ng*2);
        float4 wa0 = __ldg(WA + k*32 + cg*2);
        float4 wa1 = __ldg(WA + k*32 + cg*2 + 1);
        float4 wb0 = __ldg(WB + k*32 + cg*2);
        float4 wb1 = __ldg(WB + k*32 + cg*2 + 1);
        float wav[8] = {wa0.x,wa0.y,wa0.z,wa0.w,wa1.x,wa1.y,wa1.z,wa1.w};
        float wbv[8] = {wb0.x,wb0.y,wb0.z,wb0.w,wb1.x,wb1.y,wb1.z,wb1.w};
#pragma unroll
        for (int c = 0; c < 8; ++c) {
            accA[0][c] += a.x*wav[c]; accA[1][c] += a.y*wav[c];
            accB[0][c] += a.x*wbv[c]; accB[1][c] += a.y*wbv[c];
        }
    }
#pragma unroll
    for (int r = 0; r < 2; ++r) {
        size_t o = (size_t)(nb + ng*2 + r)*H + col;
        *(float4*)(g_A + o)     = make_float4(accA[r][0],accA[r][1],accA[r][2],accA[r][3]);
        *(float4*)(g_A + o + 4) = make_float4(accA[r][4],accA[r][5],accA[r][6],accA[r][7]);
        *(float4*)(g_B + o)     = make_float4(accB[r][0],accB[r][1],accB[r][2],accB[r][3]);
        *(float4*)(g_B + o + 4) = make_float4(accB[r][4],accB[r][5],accB[r][6],accB[r][7]);
    }
}

// ---------------- K5: fused edge MLP + gate + segment-sum (the big one) -----
// block = 128 edges = exactly 4 dst nodes; 256 threads; W2 streamed from L1/L2
__global__ __launch_bounds__(256,2) void edge_kernel(const float* __restrict__ edge_w1,
                                                     const float* __restrict__ edge_b2,
                                                     const float* __restrict__ edge_w2v,
                                                     const float* __restrict__ inf_w,
                                                     const float* __restrict__ inf_b, int l)
{
    extern __shared__ float sh[];
    float* sm1   = sh;                 // [128 k][132 e]  (k-major, padded)
    float* sW1e  = sm1 + 128*132;      // 20*128
    float* sattr = sW1e + GG*H;        // 128*20
    float* sA    = sattr + 128*GG;     // 4*128
    float* sb2   = sA + 4*H;           // 128
    float* sinfw = sb2 + H;            // 128
    float* sgate = sinfw + H;          // 128
    float* smi   = sgate + H;          // 4*128
    int*   ssrc  = (int*)(smi + 4*H);  // 128

    int tid = threadIdx.x;
    int e0 = blockIdx.x * 128;
    int d0 = e0 >> 5;
    const float* W1b = edge_w1 + (size_t)l*276*H;
    for (int i = tid; i < GG*H;   i += 256) sW1e[i]  = W1b[i];
    for (int i = tid; i < 128*GG; i += 256) sattr[i] = g_attr[(size_t)e0*GG + i];
    for (int i = tid; i < 4*H;    i += 256) { sA[i] = g_A[(size_t)d0*H + i]; smi[i] = 0.f; }
    if (tid < H) { sb2[tid] = edge_b2[l*H+tid]; sinfw[tid] = inf_w[l*H+tid]; sgate[tid] = inf_b[l]; }
    if (tid < 128) ssrc[tid] = g_nbr[e0 + tid];
    __syncthreads();

    // step A: m1[k][e] = relu(attr@W1e + A[dst] + B[src])
    {
        int e = tid >> 1, half = tid & 1;
        int src = ssrc[e];
        int d = e >> 5;
        float a20[GG];
#pragma unroll
        for (int g = 0; g < GG; ++g) a20[g] = sattr[e*GG + g];
        const float4* Brow = (const float4*)(g_B + (size_t)src*H);
#pragma unroll
        for (int i4 = 0; i4 < 16; ++i4) {
            int k0 = half*64 + i4*4;
            float4 bv = Brow[k0 >> 2];
            float vv[4] = {bv.x, bv.y, bv.z, bv.w};
#pragma unroll
            for (int j = 0; j < 4; ++j) {
                int k = k0 + j;
                float v = sA[d*H + k] + vv[j];
#pragma unroll
                for (int g = 0; g < GG; ++g) v += a20[g]*sW1e[g*H + k];
                sm1[k*132 + e] = fmaxf(v, 0.f);
            }
        }
    }
    __syncthreads();

    // step B: m = relu(m1 @ W2 + b2), 8x8 register tile per thread
    int rg = tid >> 4, cg = tid & 15;
    const float4* W2v = (const float4*)(edge_w2v + (size_t)l*H*H);
    float acc[8][8];
#pragma unroll
    for (int r = 0; r < 8; ++r)
#pragma unroll
        for (int c = 0; c < 8; ++c) acc[r][c] = 0.f;
#pragma unroll 4
    for (int k = 0; k < H; ++k) {
        float4 a0 = *(const float4*)(sm1 + k*132 + rg*8);
        float4 a1 = *(const float4*)(sm1 + k*132 + rg*8 + 4);
        float4 b0 = __ldg(W2v + k*32 + cg*2);
        float4 b1 = __ldg(W2v + k*32 + cg*2 + 1);
        float av[8]  = {a0.x,a0.y,a0.z,a0.w,a1.x,a1.y,a1.z,a1.w};
        float bvv[8] = {b0.x,b0.y,b0.z,b0.w,b1.x,b1.y,b1.z,b1.w};
#pragma unroll
        for (int r = 0; r < 8; ++r)
#pragma unroll
            for (int c = 0; c < 8; ++c) acc[r][c] += av[r]*bvv[c];
    }
#pragma unroll
    for (int r = 0; r < 8; ++r)
#pragma unroll
        for (int c = 0; c < 8; ++c) acc[r][c] = fmaxf(acc[r][c] + sb2[cg*8+c], 0.f);

    // step C: gate logits (reduce over feature dim via shared atomics)
#pragma unroll
    for (int r = 0; r < 8; ++r) {
        float p = 0.f;
#pragma unroll
        for (int c = 0; c < 8; ++c) p += acc[r][c]*sinfw[cg*8+c];
        atomicAdd(&sgate[rg*8 + r], p);
    }
    __syncthreads();
    if (tid < H) sgate[tid] = 1.f/(1.f + expf(-sgate[tid]));
    __syncthreads();

    // step D: mi[dst] = sum_e m*gate  (each thread's 8 rows live in one dst group)
    {
        int d = rg >> 2;
#pragma unroll
        for (int c = 0; c < 8; ++c) {
            float s = 0.f;
#pragma unroll
            for (int r = 0; r < 8; ++r) s += acc[r][c]*sgate[rg*8 + r];
            atomicAdd(&smi[d*H + cg*8 + c], s);
        }
    }
    __syncthreads();
    for (int i = tid; i < 4*H; i += 256) g_mi[(size_t)d0*H + i] = smi[i];
}

// ---------------- K6: node MLP + residual ----------------------------------
__global__ void __launch_bounds__(256) node_kernel(const float* __restrict__ nw1,
                                                   const float* __restrict__ nb1,
                                                   const float* __restrict__ nw2,
                                                   const float* __restrict__ nb2, int l)
{
    __shared__ float sZ[256*34];   // [mi | h] k-major, then reused for u
    int tid = threadIdx.x;
    int nb = blockIdx.x*32;
    for (int i = tid; i < 32*H; i += 256) {
        int nn = i>>7, k = i&127;
        sZ[k*34 + nn]     = g_mi[(size_t)(nb+nn)*H + k];
        sZ[(H+k)*34 + nn] = g_h [(size_t)(nb+nn)*H + k];
    }
    __syncthreads();
    int cg = tid & 15, ng = tid >> 4, col = cg*8;
    const float4* W1a = (const float4*)(nw1 + (size_t)l*2*H*H);
    const float4* W1b = W1a + H*H/4;
    float acc[2][8];
#pragma unroll
    for (int c = 0; c < 8; ++c) { float b = nb1[l*H + col + c]; acc[0][c] = b; acc[1][c] = b; }
#pragma unroll 2
    for (int k = 0; k < H; ++k) {
        float2 am = *(const float2*)(sZ + k*34 + ng*2);
        float2 ah = *(const float2*)(sZ + (H+k)*34 + ng*2);
        float4 wa0 = __ldg(W1a + k*32 + cg*2);
        float4 wa1 = __ldg(W1a + k*32 + cg*2 + 1);
        float4 wb0 = __ldg(W1b + k*32 + cg*2);
        float4 wb1 = __ldg(W1b + k*32 + cg*2 + 1);
        float wav[8] = {wa0.x,wa0.y,wa0.z,wa0.w,wa1.x,wa1.y,wa1.z,wa1.w};
        float wbv[8] = {wb0.x,wb0.y,wb0.z,wb0.w,wb1.x,wb1.y,wb1.z,wb1.w};
#pragma unroll
        for (int c = 0; c < 8; ++c) {
            acc[0][c] += am.x*wav[c] + ah.x*wbv[c];
            acc[1][c] += am.y*wav[c] + ah.y*wbv[c];
        }
    }
    __syncthreads();   // done reading sZ
#pragma unroll
    for (int r = 0; r < 2; ++r)
#pragma unroll
        for (int c = 0; c < 8; ++c) sZ[(col + c)*34 + ng*2 + r] = fmaxf(acc[r][c], 0.f);
    __syncthreads();
    const float4* W2 = (const float4*)(nw2 + (size_t)l*H*H);
    float acc2[2][8];
#pragma unroll
    for (int c = 0; c < 8; ++c) { float b = nb2[l*H + col + c]; acc2[0][c] = b; acc2[1][c] = b; }
#pragma unroll 2
    for (int k = 0; k < H; ++k) {
        float2 a  = *(const float2*)(sZ + k*34 + ng*2);
        float4 w0 = __ldg(W2 + k*32 + cg*2);
        float4 w1 = __ldg(W2 + k*32 + cg*2 + 1);
        float wv[8] = {w0.x,w0.y,w0.z,w0.w,w1.x,w1.y,w1.z,w1.w};
#pragma unroll
        for (int c = 0; c < 8; ++c) { acc2[0][c] += a.x*wv[c]; acc2[1][c] += a.y*wv[c]; }
    }
#pragma unroll
    for (int r = 0; r < 2; ++r) {
        size_t o = (size_t)(nb + ng*2 + r)*H + col;
        float4* hp = (float4*)(g_h + o);
        float4 h0 = hp[0], h1 = hp[1];
        h0.x += acc2[r][0]; h0.y += acc2[r][1]; h0.z += acc2[r][2]; h0.w += acc2[r][3];
        h1.x += acc2[r][4]; h1.y += acc2[r][5]; h1.z += acc2[r][6]; h1.w += acc2[r][7];
        hp[0] = h0; hp[1] = h1;
    }
}

// ---------------- K7: per-graph pooling (parallel + atomics) ----------------
__global__ void pool_kernel(int n)
{
    int b = blockIdx.x >> 4, s = blockIdx.x & 15;
    int c = threadIdx.x;  // 128 threads
    float acc = 0.f;
    for (int i = s; i < n; i += 16) acc += g_h[((size_t)b*n + i)*H + c];
    atomicAdd(&g_pre[b*H + c], acc);
}

// ---------------- K8: out_block + output selection ---------------------------
__global__ void out_kernel(const float* __restrict__ w1, const float* __restrict__ b1,
                           const float* __restrict__ w2, const float* __restrict__ b2,
                           const int* __restrict__ kind, float* __restrict__ out, int B)
{
    __shared__ float sU[H]; __shared__ float so[3];
    int t = threadIdx.x;
    for (int b = 0; b < B; ++b) {
        float x = b1[t];
        for (int k = 0; k < H; ++k) x += g_pre[b*H + k]*w1[k*H + t];
        float sp = (x > 0.f) ? x + log1pf(expf(-x)) : log1pf(expf(x));
        sU[t] = sp - 0.6931471805599453f;
        __syncthreads();
        if (t < 3) { float s = b2[t]; for (int k = 0; k < H; ++k) s += sU[k]*w2[k*3 + t]; so[t] = s; }
        __syncthreads();
        if (t == 0) out[b] = so[kind[b] - 1];
        __syncthreads();
    }
}

// ---------------- host ------------------------------------------------------
#define EDGE_SMEM ((128*132 + 20*128 + 128*20 + 4*128 + 128 + 128 + 128 + 4*128 + 128)*4)

extern "C" void kernel_launch(void* const* d_in, const int* in_sizes, int n_in,
                              void* d_out, int out_size)
{
    const float* protein_pos  = (const float*)d_in[0];
    const float* protein_feat = (const float*)d_in[1];
    const float* ligand_pos   = (const float*)d_in[2];
    const float* ligand_feat  = (const float*)d_in[3];
    const int*   output_kind  = (const int*)d_in[6];
    const float* prot_w = (const float*)d_in[7];  const float* prot_b = (const float*)d_in[8];
    const float* lig_w  = (const float*)d_in[9];  const float* lig_b  = (const float*)d_in[10];
    const float* edge_w1 = (const float*)d_in[11]; const float* edge_b1 = (const float*)d_in[12];
    const float* edge_w2 = (const float*)d_in[13]; const float* edge_b2 = (const float*)d_in[14];
    const float* inf_w   = (const float*)d_in[15]; const float* inf_b   = (const float*)d_in[16];
    const float* node_w1 = (const float*)d_in[17]; const float* node_b1 = (const float*)d_in[18];
    const float* node_w2 = (const float*)d_in[19]; const float* node_b2 = (const float*)d_in[20];
    const float* out_w1  = (const float*)d_in[21]; const float* out_b1  = (const float*)d_in[22];
    const float* out_w2  = (const float*)d_in[23]; const float* out_b2  = (const float*)d_in[24];
    float* out = (float*)d_out;

    int Np = in_sizes[0]/3, Nl = in_sizes[2]/3;
    int B  = in_sizes[6];
    int Fp = in_sizes[1]/Np, Fl = in_sizes[3]/Nl;
    int n_prot = Np/B, n_lig = Nl/B;
    int n = n_prot + n_lig;
    int N = Np + Nl;
    int E = N*KNN;

    cudaFuncSetAttribute(edge_kernel, cudaFuncAttributeMaxDynamicSharedMemorySize, EDGE_SMEM);

    embed_kernel<<<N, 128>>>(protein_pos, protein_feat, ligand_pos, ligand_feat,
                             prot_w, prot_b, lig_w, lig_b, n_prot, n_lig, n, Fp, Fl);

    knn_kernel<<<dim3((n + 127)/128, B), 128, n*3*sizeof(float)>>>(n);

    float step  = 10.0f/19.0f;           // CUTOFF / (G-1)
    float coeff = -0.5f/(step*step);
    attr_kernel<<<(E + 255)/256, 256>>>(E, step, coeff);

    ab_kernel<<<N/32, 256>>>(edge_w1, edge_b1, 0);
    for (int l = 0; l < 3; ++l) {
        edge_kernel<<<E/128, 256, EDGE_SMEM>>>(edge_w1, edge_b2, edge_w2, inf_w, inf_b, l);
        node_kernel<<<N/32, 256>>>(node_w1, node_b1, node_w2, node_b2, l);
        if (l < 2) ab_kernel<<<N/32, 256>>>(edge_w1, edge_b1, l + 1);
    }

    pool_kernel<<<B*16, 128>>>(n);
    out_kernel<<<1, 128>>>(out_w1, out_b1, out_w2, out_b2, output_kind, out, B);
}

// round 4
// speedup vs baseline: 1.0408x; 1.0408x over previous
#include <cuda_runtime.h>
#include <math.h>

#define H   128
#define GG  20
#define KNN 32
#define MAXN 24000
#define MAXE (MAXN*KNN)

// ---------------- scratch (static __device__, no allocation) ----------------
__device__ __align__(16) float g_pos[MAXN*3];
__device__ __align__(16) float g_h  [MAXN*H];
__device__ __align__(16) float g_A  [MAXN*H];   // h @ W1i + b1   (dst part)
__device__ __align__(16) float g_B  [MAXN*H];   // h @ W1j        (src part)
__device__ __align__(16) float g_mi [MAXN*H];
__device__ int   g_nbr[MAXE];
__device__ float g_attr[(size_t)MAXE*GG];
__device__ float g_pre[16*H];

// ---------------- K1: embeddings + composed (sorted) layout ----------------
__global__ void embed_kernel(const float* __restrict__ ppos, const float* __restrict__ pfeat,
                             const float* __restrict__ lpos, const float* __restrict__ lfeat,
                             const float* __restrict__ pw, const float* __restrict__ pb,
                             const float* __restrict__ lw, const float* __restrict__ lb,
                             int n_prot, int n_lig, int n, int Fp, int Fl)
{
    __shared__ float sf[32];
    int i = blockIdx.x, t = threadIdx.x;
    int b = i / n, j = i - b * n;
    const float *feat, *w, *bias, *pos; int F;
    if (j < n_prot) { int r = b*n_prot + j;            feat = pfeat + (size_t)r*Fp; w = pw; bias = pb; pos = ppos + (size_t)r*3; F = Fp; }
    else            { int r = b*n_lig  + (j - n_prot); feat = lfeat + (size_t)r*Fl; w = lw; bias = lb; pos = lpos + (size_t)r*3; F = Fl; }
    if (t < F) sf[t] = feat[t];
    __syncthreads();
    float acc = bias[t];
    for (int f = 0; f < F; ++f) acc += sf[f] * w[f*H + t];
    g_h[(size_t)i*H + t] = acc;
    if (t < 3) g_pos[i*3 + t] = pos[t];
}

// ---------------- K2: brute-force kNN (stable tie-break like jax top_k) -----
__global__ void knn_kernel(int n)
{
    extern __shared__ float spos[];
    int b = blockIdx.y, tid = threadIdx.x;
    const float* gp = g_pos + (size_t)b*n*3;
    for (int i = tid; i < n*3; i += blockDim.x) spos[i] = gp[i];
    __syncthreads();
    int c = blockIdx.x*blockDim.x + tid;
    if (c >= n) return;
    float cx = spos[c*3], cy = spos[c*3+1], cz = spos[c*3+2];
    float bd[KNN]; int bi[KNN];
#pragma unroll
    for (int s = 0; s < KNN; ++s) { bd[s] = 3.402823466e38f; bi[s] = 0x7fffffff; }
    float wd = 3.402823466e38f; int wi = 0x7fffffff; int ws = 0;
    for (int j = 0; j < n; ++j) {
        if (j == c) continue;
        float dx = cx - spos[j*3], dy = cy - spos[j*3+1], dz = cz - spos[j*3+2];
        float d2 = dx*dx + dy*dy + dz*dz;
        if (d2 < wd || (d2 == wd && j < wi)) {
            bd[ws] = d2; bi[ws] = j;
            wd = bd[0]; wi = bi[0]; ws = 0;
#pragma unroll
            for (int s = 1; s < KNN; ++s)
                if (bd[s] > wd || (bd[s] == wd && bi[s] > wi)) { wd = bd[s]; wi = bi[s]; ws = s; }
        }
    }
    size_t base = ((size_t)(b*n + c))*KNN;
#pragma unroll
    for (int s = 0; s < KNN; ++s) g_nbr[base + s] = b*n + bi[s];
}

// ---------------- K3: Gaussian smearing + zero g_pre ------------------------
__global__ void attr_kernel(int E, float step, float coeff)
{
    int e = blockIdx.x*blockDim.x + threadIdx.x;
    if (e >= E) return;
    if (e < 16*H) g_pre[e] = 0.f;
    int dst = e >> 5;
    int src = g_nbr[e];
    float dx = g_pos[dst*3]   - g_pos[src*3];
    float dy = g_pos[dst*3+1] - g_pos[src*3+1];
    float dz = g_pos[dst*3+2] - g_pos[src*3+2];
    float d = sqrtf(dx*dx + dy*dy + dz*dz);
    size_t o = (size_t)e*GG;
#pragma unroll
    for (int g = 0; g < GG; ++g) {
        float t = d - g*step;
        g_attr[o + g] = expf(coeff*t*t);
    }
}

// ---------------- K4: A = h@W1i + b1, B = h@W1j  (one fused k-loop) ---------
__global__ void __launch_bounds__(256) ab_kernel(const float* __restrict__ edge_w1,
                                                 const float* __restrict__ edge_b1, int l)
{
    __shared__ float sHt[128*34];
    int tid = threadIdx.x;
    int nb = blockIdx.x*32;
    for (int i = tid; i < 32*H; i += 256) { int nn = i>>7, k = i&127; sHt[k*34+nn] = g_h[(size_t)(nb+nn)*H + k]; }
    __syncthreads();
    int cg = tid & 15, ng = tid >> 4, col = cg*8;
    const float4* WA = (const float4*)(edge_w1 + (size_t)l*276*H + GG*H);
    const float4* WB = (const float4*)(edge_w1 + (size_t)l*276*H + (GG+H)*H);
    float accA[2][8], accB[2][8];
#pragma unroll
    for (int c = 0; c < 8; ++c) {
        float b0 = edge_b1[l*H + col + c];
        accA[0][c] = b0; accA[1][c] = b0; accB[0][c] = 0.f; accB[1][c] = 0.f;
    }
#pragma unroll 2
    for (int k = 0; k < H; ++k) {
        float2 a  = *(const float2*)(sHt + k*34 + ng*2);
        float4 wa0 = __ldg(WA + k*32 + cg*2);
        float4 wa1 = __ldg(WA + k*32 + cg*2 + 1);
        float4 wb0 = __ldg(WB + k*32 + cg*2);
        float4 wb1 = __ldg(WB + k*32 + cg*2 + 1);
        float wav[8] = {wa0.x,wa0.y,wa0.z,wa0.w,wa1.x,wa1.y,wa1.z,wa1.w};
        float wbv[8] = {wb0.x,wb0.y,wb0.z,wb0.w,wb1.x,wb1.y,wb1.z,wb1.w};
#pragma unroll
        for (int c = 0; c < 8; ++c) {
            accA[0][c] += a.x*wav[c]; accA[1][c] += a.y*wav[c];
            accB[0][c] += a.x*wbv[c]; accB[1][c] += a.y*wbv[c];
        }
    }
#pragma unroll
    for (int r = 0; r < 2; ++r) {
        size_t o = (size_t)(nb + ng*2 + r)*H + col;
        *(float4*)(g_A + o)     = make_float4(accA[r][0],accA[r][1],accA[r][2],accA[r][3]);
        *(float4*)(g_A + o + 4) = make_float4(accA[r][4],accA[r][5],accA[r][6],accA[r][7]);
        *(float4*)(g_B + o)     = make_float4(accB[r][0],accB[r][1],accB[r][2],accB[r][3]);
        *(float4*)(g_B + o + 4) = make_float4(accB[r][4],accB[r][5],accB[r][6],accB[r][7]);
    }
}

// ---------------- K5: fused edge MLP + gate + segment-sum (the big one) -----
// block = 128 edges = exactly 4 dst nodes; 256 threads; W2 streamed from L1/L2
__global__ __launch_bounds__(256,2) void edge_kernel(const float* __restrict__ edge_w1,
                                                     const float* __restrict__ edge_b2,
                                                     const float* __restrict__ edge_w2v,
                                                     const float* __restrict__ inf_w,
                                                     const float* __restrict__ inf_b, int l)
{
    extern __shared__ float sh[];
    float* sm1   = sh;                 // [128 k][132 e]  (k-major, padded)
    float* sW1e  = sm1 + 128*132;      // 20*128
    float* sattr = sW1e + GG*H;        // 128*20
    float* sA    = sattr + 128*GG;     // 4*128
    float* sb2   = sA + 4*H;           // 128
    float* sinfw = sb2 + H;            // 128
    float* sgate = sinfw + H;          // 128
    float* smi   = sgate + H;          // 4*128
    int*   ssrc  = (int*)(smi + 4*H);  // 128

    int tid = threadIdx.x;
    int e0 = blockIdx.x * 128;
    int d0 = e0 >> 5;
    const float* W1b = edge_w1 + (size_t)l*276*H;
    for (int i = tid; i < GG*H;   i += 256) sW1e[i]  = W1b[i];
    for (int i = tid; i < 128*GG; i += 256) sattr[i] = g_attr[(size_t)e0*GG + i];
    for (int i = tid; i < 4*H;    i += 256) { sA[i] = g_A[(size_t)d0*H + i]; smi[i] = 0.f; }
    if (tid < H) { sb2[tid] = edge_b2[l*H+tid]; sinfw[tid] = inf_w[l*H+tid]; sgate[tid] = inf_b[l]; }
    if (tid < 128) ssrc[tid] = g_nbr[e0 + tid];
    __syncthreads();

    // step A: m1[k][e] = relu(attr@W1e + A[dst] + B[src])
    {
        int e = tid >> 1, half = tid & 1;
        int src = ssrc[e];
        int d = e >> 5;
        float a20[GG];
#pragma unroll
        for (int g = 0; g < GG; ++g) a20[g] = sattr[e*GG + g];
        const float4* Brow = (const float4*)(g_B + (size_t)src*H);
#pragma unroll
        for (int i4 = 0; i4 < 16; ++i4) {
            int k0 = half*64 + i4*4;
            float4 bv = Brow[k0 >> 2];
            float vv[4] = {bv.x, bv.y, bv.z, bv.w};
#pragma unroll
            for (int j = 0; j < 4; ++j) {
                int k = k0 + j;
                float v = sA[d*H + k] + vv[j];
#pragma unroll
                for (int g = 0; g < GG; ++g) v += a20[g]*sW1e[g*H + k];
                sm1[k*132 + e] = fmaxf(v, 0.f);
            }
        }
    }
    __syncthreads();

    // step B: m = relu(m1 @ W2 + b2), 8x8 register tile per thread
    int rg = tid >> 4, cg = tid & 15;
    const float4* W2v = (const float4*)(edge_w2v + (size_t)l*H*H);
    float acc[8][8];
#pragma unroll
    for (int r = 0; r < 8; ++r)
#pragma unroll
        for (int c = 0; c < 8; ++c) acc[r][c] = 0.f;
#pragma unroll 4
    for (int k = 0; k < H; ++k) {
        float4 a0 = *(const float4*)(sm1 + k*132 + rg*8);
        float4 a1 = *(const float4*)(sm1 + k*132 + rg*8 + 4);
        float4 b0 = __ldg(W2v + k*32 + cg*2);
        float4 b1 = __ldg(W2v + k*32 + cg*2 + 1);
        float av[8]  = {a0.x,a0.y,a0.z,a0.w,a1.x,a1.y,a1.z,a1.w};
        float bvv[8] = {b0.x,b0.y,b0.z,b0.w,b1.x,b1.y,b1.z,b1.w};
#pragma unroll
        for (int r = 0; r < 8; ++r)
#pragma unroll
            for (int c = 0; c < 8; ++c) acc[r][c] += av[r]*bvv[c];
    }
#pragma unroll
    for (int r = 0; r < 8; ++r)
#pragma unroll
        for (int c = 0; c < 8; ++c) acc[r][c] = fmaxf(acc[r][c] + sb2[cg*8+c], 0.f);

    // step C: gate logits (reduce over feature dim via shared atomics)
#pragma unroll
    for (int r = 0; r < 8; ++r) {
        float p = 0.f;
#pragma unroll
        for (int c = 0; c < 8; ++c) p += acc[r][c]*sinfw[cg*8+c];
        atomicAdd(&sgate[rg*8 + r], p);
    }
    __syncthreads();
    if (tid < H) sgate[tid] = 1.f/(1.f + expf(-sgate[tid]));
    __syncthreads();

    // step D: mi[dst] = sum_e m*gate  (each thread's 8 rows live in one dst group)
    {
        int d = rg >> 2;
#pragma unroll
        for (int c = 0; c < 8; ++c) {
            float s = 0.f;
#pragma unroll
            for (int r = 0; r < 8; ++r) s += acc[r][c]*sgate[rg*8 + r];
            atomicAdd(&smi[d*H + cg*8 + c], s);
        }
    }
    __syncthreads();
    for (int i = tid; i < 4*H; i += 256) g_mi[(size_t)d0*H + i] = smi[i];
}

// ---------------- K6: node MLP + residual ----------------------------------
__global__ void __launch_bounds__(256) node_kernel(const float* __restrict__ nw1,
                                                   const float* __restrict__ nb1,
                                                   const float* __restrict__ nw2,
                                                   const float* __restrict__ nb2, int l)
{
    __shared__ float sZ[256*34];   // [mi | h] k-major, then reused for u
    int tid = threadIdx.x;
    int nb = blockIdx.x*32;
    for (int i = tid; i < 32*H; i += 256) {
        int nn = i>>7, k = i&127;
        sZ[k*34 + nn]     = g_mi[(size_t)(nb+nn)*H + k];
        sZ[(H+k)*34 + nn] = g_h [(size_t)(nb+nn)*H + k];
    }
    __syncthreads();
    int cg = tid & 15, ng = tid >> 4, col = cg*8;
    const float4* W1a = (const float4*)(nw1 + (size_t)l*2*H*H);
    const float4* W1b = W1a + H*H/4;
    float acc[2][8];
#pragma unroll
    for (int c = 0; c < 8; ++c) { float b = nb1[l*H + col + c]; acc[0][c] = b; acc[1][c] = b; }
#pragma unroll 2
    for (int k = 0; k < H; ++k) {
        float2 am = *(const float2*)(sZ + k*34 + ng*2);
        float2 ah = *(const float2*)(sZ + (H+k)*34 + ng*2);
        float4 wa0 = __ldg(W1a + k*32 + cg*2);
        float4 wa1 = __ldg(W1a + k*32 + cg*2 + 1);
        float4 wb0 = __ldg(W1b + k*32 + cg*2);
        float4 wb1 = __ldg(W1b + k*32 + cg*2 + 1);
        float wav[8] = {wa0.x,wa0.y,wa0.z,wa0.w,wa1.x,wa1.y,wa1.z,wa1.w};
        float wbv[8] = {wb0.x,wb0.y,wb0.z,wb0.w,wb1.x,wb1.y,wb1.z,wb1.w};
#pragma unroll
        for (int c = 0; c < 8; ++c) {
            acc[0][c] += am.x*wav[c] + ah.x*wbv[c];
            acc[1][c] += am.y*wav[c] + ah.y*wbv[c];
        }
    }
    __syncthreads();   // done reading sZ
#pragma unroll
    for (int r = 0; r < 2; ++r)
#pragma unroll
        for (int c = 0; c < 8; ++c) sZ[(col + c)*34 + ng*2 + r] = fmaxf(acc[r][c], 0.f);
    __syncthreads();
    const float4* W2 = (const float4*)(nw2 + (size_t)l*H*H);
    float acc2[2][8];
#pragma unroll
    for (int c = 0; c < 8; ++c) { float b = nb2[l*H + col + c]; acc2[0][c] = b; acc2[1][c] = b; }
#pragma unroll 2
    for (int k = 0; k < H; ++k) {
        float2 a  = *(const float2*)(sZ + k*34 + ng*2);
        float4 w0 = __ldg(W2 + k*32 + cg*2);
        float4 w1 = __ldg(W2 + k*32 + cg*2 + 1);
        float wv[8] = {w0.x,w0.y,w0.z,w0.w,w1.x,w1.y,w1.z,w1.w};
#pragma unroll
        for (int c = 0; c < 8; ++c) { acc2[0][c] += a.x*wv[c]; acc2[1][c] += a.y*wv[c]; }
    }
#pragma unroll
    for (int r = 0; r < 2; ++r) {
        size_t o = (size_t)(nb + ng*2 + r)*H + col;
        float4* hp = (float4*)(g_h + o);
        float4 h0 = hp[0], h1 = hp[1];
        h0.x += acc2[r][0]; h0.y += acc2[r][1]; h0.z += acc2[r][2]; h0.w += acc2[r][3];
        h1.x += acc2[r][4]; h1.y += acc2[r][5]; h1.z += acc2[r][6]; h1.w += acc2[r][7];
        hp[0] = h0; hp[1] = h1;
    }
}

// ---------------- K7: per-graph pooling (parallel + atomics) ----------------
__global__ void pool_kernel(int n)
{
    int b = blockIdx.x >> 4, s = blockIdx.x & 15;
    int c = threadIdx.x;  // 128 threads
    float acc = 0.f;
    for (int i = s; i < n; i += 16) acc += g_h[((size_t)b*n + i)*H + c];
    atomicAdd(&g_pre[b*H + c], acc);
}

// ---------------- K8: out_block + output selection ---------------------------
__global__ void out_kernel(const float* __restrict__ w1, const float* __restrict__ b1,
                           const float* __restrict__ w2, const float* __restrict__ b2,
                           const int* __restrict__ kind, float* __restrict__ out, int B)
{
    __shared__ float sU[H]; __shared__ float so[3];
    int t = threadIdx.x;
    for (int b = 0; b < B; ++b) {
        float x = b1[t];
        for (int k = 0; k < H; ++k) x += g_pre[b*H + k]*w1[k*H + t];
        float sp = (x > 0.f) ? x + log1pf(expf(-x)) : log1pf(expf(x));
        sU[t] = sp - 0.6931471805599453f;
        __syncthreads();
        if (t < 3) { float s = b2[t]; for (int k = 0; k < H; ++k) s += sU[k]*w2[k*3 + t]; so[t] = s; }
        __syncthreads();
        if (t == 0) out[b] = so[kind[b] - 1];
        __syncthreads();
    }
}

// ---------------- host ------------------------------------------------------
#define EDGE_SMEM ((128*132 + 20*128 + 128*20 + 4*128 + 128 + 128 + 128 + 4*128 + 128)*4)

extern "C" void kernel_launch(void* const* d_in, const int* in_sizes, int n_in,
                              void* d_out, int out_size)
{
    const float* protein_pos  = (const float*)d_in[0];
    const float* protein_feat = (const float*)d_in[1];
    const float* ligand_pos   = (const float*)d_in[2];
    const float* ligand_feat  = (const float*)d_in[3];
    const int*   output_kind  = (const int*)d_in[6];
    const float* prot_w = (const float*)d_in[7];  const float* prot_b = (const float*)d_in[8];
    const float* lig_w  = (const float*)d_in[9];  const float* lig_b  = (const float*)d_in[10];
    const float* edge_w1 = (const float*)d_in[11]; const float* edge_b1 = (const float*)d_in[12];
    const float* edge_w2 = (const float*)d_in[13]; const float* edge_b2 = (const float*)d_in[14];
    const float* inf_w   = (const float*)d_in[15]; const float* inf_b   = (const float*)d_in[16];
    const float* node_w1 = (const float*)d_in[17]; const float* node_b1 = (const float*)d_in[18];
    const float* node_w2 = (const float*)d_in[19]; const float* node_b2 = (const float*)d_in[20];
    const float* out_w1  = (const float*)d_in[21]; const float* out_b1  = (const float*)d_in[22];
    const float* out_w2  = (const float*)d_in[23]; const float* out_b2  = (const float*)d_in[24];
    float* out = (float*)d_out;

    int Np = in_sizes[0]/3, Nl = in_sizes[2]/3;
    int B  = in_sizes[6];
    int Fp = in_sizes[1]/Np, Fl = in_sizes[3]/Nl;
    int n_prot = Np/B, n_lig = Nl/B;
    int n = n_prot + n_lig;
    int N = Np + Nl;
    int E = N*KNN;

    cudaFuncSetAttribute(edge_kernel, cudaFuncAttributeMaxDynamicSharedMemorySize, EDGE_SMEM);

    embed_kernel<<<N, 128>>>(protein_pos, protein_feat, ligand_pos, ligand_feat,
                             prot_w, prot_b, lig_w, lig_b, n_prot, n_lig, n, Fp, Fl);

    knn_kernel<<<dim3((n + 127)/128, B), 128, n*3*sizeof(float)>>>(n);

    float step  = 10.0f/19.0f;           // CUTOFF / (G-1)
    float coeff = -0.5f/(step*step);
    attr_kernel<<<(E + 255)/256, 256>>>(E, step, coeff);

    ab_kernel<<<N/32, 256>>>(edge_w1, edge_b1, 0);
    for (int l = 0; l < 3; ++l) {
        edge_kernel<<<E/128, 256, EDGE_SMEM>>>(edge_w1, edge_b2, edge_w2, inf_w, inf_b, l);
        node_kernel<<<N/32, 256>>>(node_w1, node_b1, node_w2, node_b2, l);
        if (l < 2) ab_kernel<<<N/32, 256>>>(edge_w1, edge_b1, l + 1);
    }

    pool_kernel<<<B*16, 128>>>(n);
    out_kernel<<<1, 128>>>(out_w1, out_b1, out_w2, out_b2, output_kind, out, B);
}

// round 5
// speedup vs baseline: 1.0451x; 1.0041x over previous
#include <cuda_runtime.h>
#include <math.h>

#define H   128
#define GG  20
#define KNN 32
#define MAXN 24000
#define MAXE (MAXN*KNN)

// ---------------- scratch (static __device__, no allocation) ----------------
__device__ __align__(16) float g_pos[MAXN*3];
__device__ __align__(16) float g_h  [MAXN*H];
__device__ __align__(16) float g_A  [MAXN*H];   // h @ W1i + b1   (dst part)
__device__ __align__(16) float g_B  [MAXN*H];   // h @ W1j        (src part)
__device__ __align__(16) float g_mi [MAXN*H];
__device__ int   g_nbr[MAXE];
__device__ float g_attr[(size_t)MAXE*GG];
__device__ float g_pre[16*H];

// ---------------- K1: embeddings + composed (sorted) layout ----------------
__global__ void embed_kernel(const float* __restrict__ ppos, const float* __restrict__ pfeat,
                             const float* __restrict__ lpos, const float* __restrict__ lfeat,
                             const float* __restrict__ pw, const float* __restrict__ pb,
                             const float* __restrict__ lw, const float* __restrict__ lb,
                             int n_prot, int n_lig, int n, int Fp, int Fl)
{
    __shared__ float sf[32];
    int i = blockIdx.x, t = threadIdx.x;
    int b = i / n, j = i - b * n;
    const float *feat, *w, *bias, *pos; int F;
    if (j < n_prot) { int r = b*n_prot + j;            feat = pfeat + (size_t)r*Fp; w = pw; bias = pb; pos = ppos + (size_t)r*3; F = Fp; }
    else            { int r = b*n_lig  + (j - n_prot); feat = lfeat + (size_t)r*Fl; w = lw; bias = lb; pos = lpos + (size_t)r*3; F = Fl; }
    if (t < F) sf[t] = feat[t];
    __syncthreads();
    float acc = bias[t];
    for (int f = 0; f < F; ++f) acc += sf[f] * w[f*H + t];
    g_h[(size_t)i*H + t] = acc;
    if (t < 3) g_pos[i*3 + t] = pos[t];
}

// ---------------- K2: brute-force kNN (stable tie-break like jax top_k) -----
__global__ void knn_kernel(int n)
{
    extern __shared__ float spos[];
    int b = blockIdx.y, tid = threadIdx.x;
    const float* gp = g_pos + (size_t)b*n*3;
    for (int i = tid; i < n*3; i += blockDim.x) spos[i] = gp[i];
    __syncthreads();
    int c = blockIdx.x*blockDim.x + tid;
    if (c >= n) return;
    float cx = spos[c*3], cy = spos[c*3+1], cz = spos[c*3+2];
    float bd[KNN]; int bi[KNN];
#pragma unroll
    for (int s = 0; s < KNN; ++s) { bd[s] = 3.402823466e38f; bi[s] = 0x7fffffff; }
    float wd = 3.402823466e38f; int wi = 0x7fffffff; int ws = 0;
    for (int j = 0; j < n; ++j) {
        if (j == c) continue;
        float dx = cx - spos[j*3], dy = cy - spos[j*3+1], dz = cz - spos[j*3+2];
        float d2 = dx*dx + dy*dy + dz*dz;
        if (d2 < wd || (d2 == wd && j < wi)) {
            bd[ws] = d2; bi[ws] = j;
            wd = bd[0]; wi = bi[0]; ws = 0;
#pragma unroll
            for (int s = 1; s < KNN; ++s)
                if (bd[s] > wd || (bd[s] == wd && bi[s] > wi)) { wd = bd[s]; wi = bi[s]; ws = s; }
        }
    }
    size_t base = ((size_t)(b*n + c))*KNN;
#pragma unroll
    for (int s = 0; s < KNN; ++s) g_nbr[base + s] = b*n + bi[s];
}

// ---------------- K3: Gaussian smearing + zero g_pre ------------------------
__global__ void attr_kernel(int E, float step, float coeff)
{
    int e = blockIdx.x*blockDim.x + threadIdx.x;
    if (e >= E) return;
    if (e < 16*H) g_pre[e] = 0.f;
    int dst = e >> 5;
    int src = g_nbr[e];
    float dx = g_pos[dst*3]   - g_pos[src*3];
    float dy = g_pos[dst*3+1] - g_pos[src*3+1];
    float dz = g_pos[dst*3+2] - g_pos[src*3+2];
    float d = sqrtf(dx*dx + dy*dy + dz*dz);
    size_t o = (size_t)e*GG;
#pragma unroll
    for (int g = 0; g < GG; ++g) {
        float t = d - g*step;
        g_attr[o + g] = expf(coeff*t*t);
    }
}

// ---------------- K4: A = h@W1i + b1, B = h@W1j  (one fused k-loop) ---------
__global__ void __launch_bounds__(256) ab_kernel(const float* __restrict__ edge_w1,
                                                 const float* __restrict__ edge_b1, int l)
{
    __shared__ float sHt[128*34];
    int tid = threadIdx.x;
    int nb = blockIdx.x*32;
    for (int i = tid; i < 32*H; i += 256) { int nn = i>>7, k = i&127; sHt[k*34+nn] = g_h[(size_t)(nb+nn)*H + k]; }
    __syncthreads();
    int cg = tid & 15, ng = tid >> 4, col = cg*8;
    const float4* WA = (const float4*)(edge_w1 + (size_t)l*276*H + GG*H);
    const float4* WB = (const float4*)(edge_w1 + (size_t)l*276*H + (GG+H)*H);
    float accA[2][8], accB[2][8];
#pragma unroll
    for (int c = 0; c < 8; ++c) {
        float b0 = edge_b1[l*H + col + c];
        accA[0][c] = b0; accA[1][c] = b0; accB[0][c] = 0.f; accB[1][c] = 0.f;
    }
#pragma unroll 2
    for (int k = 0; k < H; ++k) {
        float2 a  = *(const float2*)(sHt + k*34 + ng*2);
        float4 wa0 = __ldg(WA + k*32 + cg*2);
        float4 wa1 = __ldg(WA + k*32 + cg*2 + 1);
        float4 wb0 = __ldg(WB + k*32 + cg*2);
        float4 wb1 = __ldg(WB + k*32 + cg*2 + 1);
        float wav[8] = {wa0.x,wa0.y,wa0.z,wa0.w,wa1.x,wa1.y,wa1.z,wa1.w};
        float wbv[8] = {wb0.x,wb0.y,wb0.z,wb0.w,wb1.x,wb1.y,wb1.z,wb1.w};
#pragma unroll
        for (int c = 0; c < 8; ++c) {
            accA[0][c] += a.x*wav[c]; accA[1][c] += a.y*wav[c];
            accB[0][c] += a.x*wbv[c]; accB[1][c] += a.y*wbv[c];
        }
    }
#pragma unroll
    for (int r = 0; r < 2; ++r) {
        size_t o = (size_t)(nb + ng*2 + r)*H + col;
        *(float4*)(g_A + o)     = make_float4(accA[r][0],accA[r][1],accA[r][2],accA[r][3]);
        *(float4*)(g_A + o + 4) = make_float4(accA[r][4],accA[r][5],accA[r][6],accA[r][7]);
        *(float4*)(g_B + o)     = make_float4(accB[r][0],accB[r][1],accB[r][2],accB[r][3]);
        *(float4*)(g_B + o + 4) = make_float4(accB[r][4],accB[r][5],accB[r][6],accB[r][7]);
    }
}

// ---------------- K5: fused edge MLP + gate + segment-sum (the big one) -----
// block = 128 edges = exactly 4 dst nodes; 256 threads; W2 streamed from L1/L2
__global__ __launch_bounds__(256,2) void edge_kernel(const float* __restrict__ edge_w1,
                                                     const float* __restrict__ edge_b2,
                                                     const float* __restrict__ edge_w2v,
                                                     const float* __restrict__ inf_w,
                                                     const float* __restrict__ inf_b, int l)
{
    extern __shared__ float sh[];
    float* sm1   = sh;                 // [128 k][132 e]  (k-major, padded)
    float* sW1e  = sm1 + 128*132;      // 20*128
    float* sattr = sW1e + GG*H;        // 128*20
    float* sA    = sattr + 128*GG;     // 4*128
    float* sb2   = sA + 4*H;           // 128
    float* sinfw = sb2 + H;            // 128
    float* sgate = sinfw + H;          // 128
    float* smi   = sgate + H;          // 4*128
    int*   ssrc  = (int*)(smi + 4*H);  // 128

    int tid = threadIdx.x;
    int e0 = blockIdx.x * 128;
    int d0 = e0 >> 5;
    const float* W1b = edge_w1 + (size_t)l*276*H;
    for (int i = tid; i < GG*H;   i += 256) sW1e[i]  = W1b[i];
    for (int i = tid; i < 128*GG; i += 256) sattr[i] = g_attr[(size_t)e0*GG + i];
    for (int i = tid; i < 4*H;    i += 256) { sA[i] = g_A[(size_t)d0*H + i]; smi[i] = 0.f; }
    if (tid < H) { sb2[tid] = edge_b2[l*H+tid]; sinfw[tid] = inf_w[l*H+tid]; sgate[tid] = inf_b[l]; }
    if (tid < 128) ssrc[tid] = g_nbr[e0 + tid];
    __syncthreads();

    // step A: m1[k][e] = relu(attr@W1e + A[dst] + B[src])
    {
        int e = tid >> 1, half = tid & 1;
        int src = ssrc[e];
        int d = e >> 5;
        float a20[GG];
#pragma unroll
        for (int g = 0; g < GG; ++g) a20[g] = sattr[e*GG + g];
        const float4* Brow = (const float4*)(g_B + (size_t)src*H);
#pragma unroll
        for (int i4 = 0; i4 < 16; ++i4) {
            int k0 = half*64 + i4*4;
            float4 bv = Brow[k0 >> 2];
            float vv[4] = {bv.x, bv.y, bv.z, bv.w};
#pragma unroll
            for (int j = 0; j < 4; ++j) {
                int k = k0 + j;
                float v = sA[d*H + k] + vv[j];
#pragma unroll
                for (int g = 0; g < GG; ++g) v += a20[g]*sW1e[g*H + k];
                sm1[k*132 + e] = fmaxf(v, 0.f);
            }
        }
    }
    __syncthreads();

    // step B: m = relu(m1 @ W2 + b2), 8x8 register tile per thread
    int rg = tid >> 4, cg = tid & 15;
    const float4* W2v = (const float4*)(edge_w2v + (size_t)l*H*H);
    float acc[8][8];
#pragma unroll
    for (int r = 0; r < 8; ++r)
#pragma unroll
        for (int c = 0; c < 8; ++c) acc[r][c] = 0.f;
#pragma unroll 4
    for (int k = 0; k < H; ++k) {
        float4 a0 = *(const float4*)(sm1 + k*132 + rg*8);
        float4 a1 = *(const float4*)(sm1 + k*132 + rg*8 + 4);
        float4 b0 = __ldg(W2v + k*32 + cg*2);
        float4 b1 = __ldg(W2v + k*32 + cg*2 + 1);
        float av[8]  = {a0.x,a0.y,a0.z,a0.w,a1.x,a1.y,a1.z,a1.w};
        float bvv[8] = {b0.x,b0.y,b0.z,b0.w,b1.x,b1.y,b1.z,b1.w};
#pragma unroll
        for (int r = 0; r < 8; ++r)
#pragma unroll
            for (int c = 0; c < 8; ++c) acc[r][c] += av[r]*bvv[c];
    }
#pragma unroll
    for (int r = 0; r < 8; ++r)
#pragma unroll
        for (int c = 0; c < 8; ++c) acc[r][c] = fmaxf(acc[r][c] + sb2[cg*8+c], 0.f);

    // step C: gate logits (reduce over feature dim via shared atomics)
#pragma unroll
    for (int r = 0; r < 8; ++r) {
        float p = 0.f;
#pragma unroll
        for (int c = 0; c < 8; ++c) p += acc[r][c]*sinfw[cg*8+c];
        atomicAdd(&sgate[rg*8 + r], p);
    }
    __syncthreads();
    if (tid < H) sgate[tid] = 1.f/(1.f + expf(-sgate[tid]));
    __syncthreads();

    // step D: mi[dst] = sum_e m*gate  (each thread's 8 rows live in one dst group)
    {
        int d = rg >> 2;
#pragma unroll
        for (int c = 0; c < 8; ++c) {
            float s = 0.f;
#pragma unroll
            for (int r = 0; r < 8; ++r) s += acc[r][c]*sgate[rg*8 + r];
            atomicAdd(&smi[d*H + cg*8 + c], s);
        }
    }
    __syncthreads();
    for (int i = tid; i < 4*H; i += 256) g_mi[(size_t)d0*H + i] = smi[i];
}

// ---------------- K6: node MLP + residual ----------------------------------
__global__ void __launch_bounds__(256) node_kernel(const float* __restrict__ nw1,
                                                   const float* __restrict__ nb1,
                                                   const float* __restrict__ nw2,
                                                   const float* __restrict__ nb2, int l)
{
    __shared__ float sZ[256*34];   // [mi | h] k-major, then reused for u
    int tid = threadIdx.x;
    int nb = blockIdx.x*32;
    for (int i = tid; i < 32*H; i += 256) {
        int nn = i>>7, k = i&127;
        sZ[k*34 + nn]     = g_mi[(size_t)(nb+nn)*H + k];
        sZ[(H+k)*34 + nn] = g_h [(size_t)(nb+nn)*H + k];
    }
    __syncthreads();
    int cg = tid & 15, ng = tid >> 4, col = cg*8;
    const float4* W1a = (const float4*)(nw1 + (size_t)l*2*H*H);
    const float4* W1b = W1a + H*H/4;
    float acc[2][8];
#pragma unroll
    for (int c = 0; c < 8; ++c) { float b = nb1[l*H + col + c]; acc[0][c] = b; acc[1][c] = b; }
#pragma unroll 2
    for (int k = 0; k < H; ++k) {
        float2 am = *(const float2*)(sZ + k*34 + ng*2);
        float2 ah = *(const float2*)(sZ + (H+k)*34 + ng*2);
        float4 wa0 = __ldg(W1a + k*32 + cg*2);
        float4 wa1 = __ldg(W1a + k*32 + cg*2 + 1);
        float4 wb0 = __ldg(W1b + k*32 + cg*2);
        float4 wb1 = __ldg(W1b + k*32 + cg*2 + 1);
        float wav[8] = {wa0.x,wa0.y,wa0.z,wa0.w,wa1.x,wa1.y,wa1.z,wa1.w};
        float wbv[8] = {wb0.x,wb0.y,wb0.z,wb0.w,wb1.x,wb1.y,wb1.z,wb1.w};
#pragma unroll
        for (int c = 0; c < 8; ++c) {
            acc[0][c] += am.x*wav[c] + ah.x*wbv[c];
            acc[1][c] += am.y*wav[c] + ah.y*wbv[c];
        }
    }
    __syncthreads();   // done reading sZ
#pragma unroll
    for (int r = 0; r < 2; ++r)
#pragma unroll
        for (int c = 0; c < 8; ++c) sZ[(col + c)*34 + ng*2 + r] = fmaxf(acc[r][c], 0.f);
    __syncthreads();
    const float4* W2 = (const float4*)(nw2 + (size_t)l*H*H);
    float acc2[2][8];
#pragma unroll
    for (int c = 0; c < 8; ++c) { float b = nb2[l*H + col + c]; acc2[0][c] = b; acc2[1][c] = b; }
#pragma unroll 2
    for (int k = 0; k < H; ++k) {
        float2 a  = *(const float2*)(sZ + k*34 + ng*2);
        float4 w0 = __ldg(W2 + k*32 + cg*2);
        float4 w1 = __ldg(W2 + k*32 + cg*2 + 1);
        float wv[8] = {w0.x,w0.y,w0.z,w0.w,w1.x,w1.y,w1.z,w1.w};
#pragma unroll
        for (int c = 0; c < 8; ++c) { acc2[0][c] += a.x*wv[c]; acc2[1][c] += a.y*wv[c]; }
    }
#pragma unroll
    for (int r = 0; r < 2; ++r) {
        size_t o = (size_t)(nb + ng*2 + r)*H + col;
        float4* hp = (float4*)(g_h + o);
        float4 h0 = hp[0], h1 = hp[1];
        h0.x += acc2[r][0]; h0.y += acc2[r][1]; h0.z += acc2[r][2]; h0.w += acc2[r][3];
        h1.x += acc2[r][4]; h1.y += acc2[r][5]; h1.z += acc2[r][6]; h1.w += acc2[r][7];
        hp[0] = h0; hp[1] = h1;
    }
}

// ---------------- K7: per-graph pooling (parallel + atomics) ----------------
__global__ void pool_kernel(int n)
{
    int b = blockIdx.x >> 4, s = blockIdx.x & 15;
    int c = threadIdx.x;  // 128 threads
    float acc = 0.f;
    for (int i = s; i < n; i += 16) acc += g_h[((size_t)b*n + i)*H + c];
    atomicAdd(&g_pre[b*H + c], acc);
}

// ---------------- K8: out_block + output selection ---------------------------
__global__ void out_kernel(const float* __restrict__ w1, const float* __restrict__ b1,
                           const float* __restrict__ w2, const float* __restrict__ b2,
                           const int* __restrict__ kind, float* __restrict__ out, int B)
{
    __shared__ float sU[H]; __shared__ float so[3];
    int t = threadIdx.x;
    for (int b = 0; b < B; ++b) {
        float x = b1[t];
        for (int k = 0; k < H; ++k) x += g_pre[b*H + k]*w1[k*H + t];
        float sp = (x > 0.f) ? x + log1pf(expf(-x)) : log1pf(expf(x));
        sU[t] = sp - 0.6931471805599453f;
        __syncthreads();
        if (t < 3) { float s = b2[t]; for (int k = 0; k < H; ++k) s += sU[k]*w2[k*3 + t]; so[t] = s; }
        __syncthreads();
        if (t == 0) out[b] = so[kind[b] - 1];
        __syncthreads();
    }
}

// ---------------- host ------------------------------------------------------
#define EDGE_SMEM ((128*132 + 20*128 + 128*20 + 4*128 + 128 + 128 + 128 + 4*128 + 128)*4)

extern "C" void kernel_launch(void* const* d_in, const int* in_sizes, int n_in,
                              void* d_out, int out_size)
{
    const float* protein_pos  = (const float*)d_in[0];
    const float* protein_feat = (const float*)d_in[1];
    const float* ligand_pos   = (const float*)d_in[2];
    const float* ligand_feat  = (const float*)d_in[3];
    const int*   output_kind  = (const int*)d_in[6];
    const float* prot_w = (const float*)d_in[7];  const float* prot_b = (const float*)d_in[8];
    const float* lig_w  = (const float*)d_in[9];  const float* lig_b  = (const float*)d_in[10];
    const float* edge_w1 = (const float*)d_in[11]; const float* edge_b1 = (const float*)d_in[12];
    const float* edge_w2 = (const float*)d_in[13]; const float* edge_b2 = (const float*)d_in[14];
    const float* inf_w   = (const float*)d_in[15]; const float* inf_b   = (const float*)d_in[16];
    const float* node_w1 = (const float*)d_in[17]; const float* node_b1 = (const float*)d_in[18];
    const float* node_w2 = (const float*)d_in[19]; const float* node_b2 = (const float*)d_in[20];
    const float* out_w1  = (const float*)d_in[21]; const float* out_b1  = (const float*)d_in[22];
    const float* out_w2  = (const float*)d_in[23]; const float* out_b2  = (const float*)d_in[24];
    float* out = (float*)d_out;

    int Np = in_sizes[0]/3, Nl = in_sizes[2]/3;
    int B  = in_sizes[6];
    int Fp = in_sizes[1]/Np, Fl = in_sizes[3]/Nl;
    int n_prot = Np/B, n_lig = Nl/B;
    int n = n_prot + n_lig;
    int N = Np + Nl;
    int E = N*KNN;

    cudaFuncSetAttribute(edge_kernel, cudaFuncAttributeMaxDynamicSharedMemorySize, EDGE_SMEM);

    embed_kernel<<<N, 128>>>(protein_pos, protein_feat, ligand_pos, ligand_feat,
                             prot_w, prot_b, lig_w, lig_b, n_prot, n_lig, n, Fp, Fl);

    knn_kernel<<<dim3((n + 127)/128, B), 128, n*3*sizeof(float)>>>(n);

    float step  = 10.0f/19.0f;           // CUTOFF / (G-1)
    float coeff = -0.5f/(step*step);
    attr_kernel<<<(E + 255)/256, 256>>>(E, step, coeff);

    ab_kernel<<<N/32, 256>>>(edge_w1, edge_b1, 0);
    for (int l = 0; l < 3; ++l) {
        edge_kernel<<<E/128, 256, EDGE_SMEM>>>(edge_w1, edge_b2, edge_w2, inf_w, inf_b, l);
        node_kernel<<<N/32, 256>>>(node_w1, node_b1, node_w2, node_b2, l);
        if (l < 2) ab_kernel<<<N/32, 256>>>(edge_w1, edge_b1, l + 1);
    }

    pool_kernel<<<B*16, 128>>>(n);
    out_kernel<<<1, 128>>>(out_w1, out_b1, out_w2, out_b2, output_kind, out, B);
}

// round 6
// speedup vs baseline: 1.1443x; 1.0950x over previous
#include <cuda_runtime.h>
#include <math.h>

#define H   128
#define GG  20
#define KNN 32
#define MAXN 24000
#define MAXE (MAXN*KNN)

// ---------------- f32x2 packed helpers (FFMA2 — PTX-only on sm_103a) --------
__device__ __forceinline__ unsigned long long pack2(float lo, float hi) {
    unsigned long long r;
    asm("mov.b64 %0, {%1, %2};" : "=l"(r) : "f"(lo), "f"(hi));
    return r;
}
__device__ __forceinline__ unsigned long long dup2(float v) {
    unsigned long long r;
    asm("mov.b64 %0, {%1, %1};" : "=l"(r) : "f"(v));
    return r;
}
__device__ __forceinline__ void unpack2(unsigned long long p, float& lo, float& hi) {
    asm("mov.b64 {%0, %1}, %2;" : "=f"(lo), "=f"(hi) : "l"(p));
}
__device__ __forceinline__ unsigned long long fma2(unsigned long long a, unsigned long long b, unsigned long long c) {
    unsigned long long d;
    asm("fma.rn.f32x2 %0, %1, %2, %3;" : "=l"(d) : "l"(a), "l"(b), "l"(c));
    return d;
}
__device__ __forceinline__ unsigned long long add2(unsigned long long a, unsigned long long b) {
    unsigned long long d;
    asm("add.rn.f32x2 %0, %1, %2;" : "=l"(d) : "l"(a), "l"(b));
    return d;
}

// ---------------- scratch (static __device__, no allocation) ----------------
__device__ __align__(16) float g_pos[MAXN*3];
__device__ __align__(16) float g_h  [MAXN*H];
__device__ __align__(16) float g_A  [MAXN*H];   // h @ W1i + b1   (dst part)
__device__ __align__(16) float g_B  [MAXN*H];   // h @ W1j        (src part)
__device__ __align__(16) float g_mi [MAXN*H];
__device__ int   g_nbr[MAXE];
__device__ float g_attr[(size_t)MAXE*GG];
__device__ float g_pre[16*H];

// ---------------- K1: embeddings + composed (sorted) layout ----------------
__global__ void embed_kernel(const float* __restrict__ ppos, const float* __restrict__ pfeat,
                             const float* __restrict__ lpos, const float* __restrict__ lfeat,
                             const float* __restrict__ pw, const float* __restrict__ pb,
                             const float* __restrict__ lw, const float* __restrict__ lb,
                             int n_prot, int n_lig, int n, int Fp, int Fl)
{
    __shared__ float sf[32];
    int i = blockIdx.x, t = threadIdx.x;
    int b = i / n, j = i - b * n;
    const float *feat, *w, *bias, *pos; int F;
    if (j < n_prot) { int r = b*n_prot + j;            feat = pfeat + (size_t)r*Fp; w = pw; bias = pb; pos = ppos + (size_t)r*3; F = Fp; }
    else            { int r = b*n_lig  + (j - n_prot); feat = lfeat + (size_t)r*Fl; w = lw; bias = lb; pos = lpos + (size_t)r*3; F = Fl; }
    if (t < F) sf[t] = feat[t];
    __syncthreads();
    float acc = bias[t];
    for (int f = 0; f < F; ++f) acc += sf[f] * w[f*H + t];
    g_h[(size_t)i*H + t] = acc;
    if (t < 3) g_pos[i*3 + t] = pos[t];
}

// ---------------- K2: brute-force kNN (stable tie-break like jax top_k) -----
__global__ void knn_kernel(int n)
{
    extern __shared__ float spos[];
    int b = blockIdx.y, tid = threadIdx.x;
    const float* gp = g_pos + (size_t)b*n*3;
    for (int i = tid; i < n*3; i += blockDim.x) spos[i] = gp[i];
    __syncthreads();
    int c = blockIdx.x*blockDim.x + tid;
    if (c >= n) return;
    float cx = spos[c*3], cy = spos[c*3+1], cz = spos[c*3+2];
    float bd[KNN]; int bi[KNN];
#pragma unroll
    for (int s = 0; s < KNN; ++s) { bd[s] = 3.402823466e38f; bi[s] = 0x7fffffff; }
    float wd = 3.402823466e38f; int wi = 0x7fffffff; int ws = 0;
    for (int j = 0; j < n; ++j) {
        if (j == c) continue;
        float dx = cx - spos[j*3], dy = cy - spos[j*3+1], dz = cz - spos[j*3+2];
        float d2 = dx*dx + dy*dy + dz*dz;
        if (d2 < wd || (d2 == wd && j < wi)) {
            bd[ws] = d2; bi[ws] = j;
            wd = bd[0]; wi = bi[0]; ws = 0;
#pragma unroll
            for (int s = 1; s < KNN; ++s)
                if (bd[s] > wd || (bd[s] == wd && bi[s] > wi)) { wd = bd[s]; wi = bi[s]; ws = s; }
        }
    }
    size_t base = ((size_t)(b*n + c))*KNN;
#pragma unroll
    for (int s = 0; s < KNN; ++s) g_nbr[base + s] = b*n + bi[s];
}

// ---------------- K3: Gaussian smearing + zero g_pre ------------------------
__global__ void attr_kernel(int E, float step, float coeff)
{
    int e = blockIdx.x*blockDim.x + threadIdx.x;
    if (e >= E) return;
    if (e < 16*H) g_pre[e] = 0.f;
    int dst = e >> 5;
    int src = g_nbr[e];
    float dx = g_pos[dst*3]   - g_pos[src*3];
    float dy = g_pos[dst*3+1] - g_pos[src*3+1];
    float dz = g_pos[dst*3+2] - g_pos[src*3+2];
    float d = sqrtf(dx*dx + dy*dy + dz*dz);
    size_t o = (size_t)e*GG;
#pragma unroll
    for (int g = 0; g < GG; ++g) {
        float t = d - g*step;
        g_attr[o + g] = expf(coeff*t*t);
    }
}

// ---------------- K4: A = h@W1i + b1, B = h@W1j  (packed f32x2) -------------
__global__ void __launch_bounds__(256) ab_kernel(const float* __restrict__ edge_w1,
                                                 const float* __restrict__ edge_b1, int l)
{
    __shared__ float sHt[128*34];
    int tid = threadIdx.x;
    int nb = blockIdx.x*32;
    for (int i = tid; i < 32*H; i += 256) { int nn = i>>7, k = i&127; sHt[k*34+nn] = g_h[(size_t)(nb+nn)*H + k]; }
    __syncthreads();
    int cg = tid & 15, ng = tid >> 4, col = cg*8;
    const ulonglong2* WA = (const ulonglong2*)(edge_w1 + (size_t)l*276*H + GG*H);
    const ulonglong2* WB = (const ulonglong2*)(edge_w1 + (size_t)l*276*H + (GG+H)*H);
    unsigned long long accA[2][4], accB[2][4];
#pragma unroll
    for (int c2 = 0; c2 < 4; ++c2) {
        unsigned long long b0 = pack2(edge_b1[l*H + col + 2*c2], edge_b1[l*H + col + 2*c2 + 1]);
        accA[0][c2] = b0; accA[1][c2] = b0; accB[0][c2] = 0ull; accB[1][c2] = 0ull;
    }
#pragma unroll 4
    for (int k = 0; k < H; ++k) {
        float2 a = *(const float2*)(sHt + k*34 + ng*2);
        ulonglong2 wa0 = __ldg(WA + k*32 + cg*2);
        ulonglong2 wa1 = __ldg(WA + k*32 + cg*2 + 1);
        ulonglong2 wb0 = __ldg(WB + k*32 + cg*2);
        ulonglong2 wb1 = __ldg(WB + k*32 + cg*2 + 1);
        unsigned long long a0 = dup2(a.x), a1 = dup2(a.y);
        unsigned long long wap[4] = {wa0.x, wa0.y, wa1.x, wa1.y};
        unsigned long long wbp[4] = {wb0.x, wb0.y, wb1.x, wb1.y};
#pragma unroll
        for (int c2 = 0; c2 < 4; ++c2) {
            accA[0][c2] = fma2(a0, wap[c2], accA[0][c2]);
            accA[1][c2] = fma2(a1, wap[c2], accA[1][c2]);
            accB[0][c2] = fma2(a0, wbp[c2], accB[0][c2]);
            accB[1][c2] = fma2(a1, wbp[c2], accB[1][c2]);
        }
    }
#pragma unroll
    for (int r = 0; r < 2; ++r) {
        float va[8], vb[8];
#pragma unroll
        for (int c2 = 0; c2 < 4; ++c2) {
            unpack2(accA[r][c2], va[2*c2], va[2*c2+1]);
            unpack2(accB[r][c2], vb[2*c2], vb[2*c2+1]);
        }
        size_t o = (size_t)(nb + ng*2 + r)*H + col;
        *(float4*)(g_A + o)     = make_float4(va[0],va[1],va[2],va[3]);
        *(float4*)(g_A + o + 4) = make_float4(va[4],va[5],va[6],va[7]);
        *(float4*)(g_B + o)     = make_float4(vb[0],vb[1],vb[2],vb[3]);
        *(float4*)(g_B + o + 4) = make_float4(vb[4],vb[5],vb[6],vb[7]);
    }
}

// ---------------- K5: fused edge MLP + gate + segment-sum (packed f32x2) ----
// block = 128 edges = exactly 4 dst nodes; 256 threads; W2 streamed from L1/L2
__global__ __launch_bounds__(256,2) void edge_kernel(const float* __restrict__ edge_w1,
                                                     const float* __restrict__ edge_b2,
                                                     const float* __restrict__ edge_w2v,
                                                     const float* __restrict__ inf_w,
                                                     const float* __restrict__ inf_b, int l)
{
    extern __shared__ float sh[];
    float* sm1   = sh;                 // [128 k][132 e]  (k-major, padded)
    float* sW1e  = sm1 + 128*132;      // 20*128
    float* sattr = sW1e + GG*H;        // 128*20
    float* sA    = sattr + 128*GG;     // 4*128
    float* sb2   = sA + 4*H;           // 128
    float* sinfw = sb2 + H;            // 128
    float* sgate = sinfw + H;          // 128
    float* smi   = sgate + H;          // 4*128
    int*   ssrc  = (int*)(smi + 4*H);  // 128

    int tid = threadIdx.x;
    int e0 = blockIdx.x * 128;
    int d0 = e0 >> 5;
    const float* W1b = edge_w1 + (size_t)l*276*H;
    for (int i = tid; i < GG*H;   i += 256) sW1e[i]  = W1b[i];
    for (int i = tid; i < 128*GG; i += 256) sattr[i] = g_attr[(size_t)e0*GG + i];
    for (int i = tid; i < 4*H;    i += 256) { sA[i] = g_A[(size_t)d0*H + i]; smi[i] = 0.f; }
    if (tid < H) { sb2[tid] = edge_b2[l*H+tid]; sinfw[tid] = inf_w[l*H+tid]; sgate[tid] = inf_b[l]; }
    if (tid < 128) ssrc[tid] = g_nbr[e0 + tid];
    __syncthreads();

    // step A: m1[k][e] = relu(attr@W1e + A[dst] + B[src]), packed over k-pairs
    {
        int e = tid >> 1, half = tid & 1;
        int src = ssrc[e];
        int d = e >> 5;
        unsigned long long a20d[GG];
#pragma unroll
        for (int g = 0; g < GG; ++g) a20d[g] = dup2(sattr[e*GG + g]);
        const float4* Brow = (const float4*)(g_B + (size_t)src*H);
#pragma unroll 2
        for (int i4 = 0; i4 < 16; ++i4) {
            int k0 = half*64 + i4*4;
            float4 bv = Brow[k0 >> 2];
            unsigned long long v0 = add2(*(const unsigned long long*)(sA + d*H + k0),     pack2(bv.x, bv.y));
            unsigned long long v1 = add2(*(const unsigned long long*)(sA + d*H + k0 + 2), pack2(bv.z, bv.w));
#pragma unroll
            for (int g = 0; g < GG; ++g) {
                v0 = fma2(a20d[g], *(const unsigned long long*)(sW1e + g*H + k0),     v0);
                v1 = fma2(a20d[g], *(const unsigned long long*)(sW1e + g*H + k0 + 2), v1);
            }
            float x0, x1, x2, x3;
            unpack2(v0, x0, x1); unpack2(v1, x2, x3);
            sm1[(k0+0)*132 + e] = fmaxf(x0, 0.f);
            sm1[(k0+1)*132 + e] = fmaxf(x1, 0.f);
            sm1[(k0+2)*132 + e] = fmaxf(x2, 0.f);
            sm1[(k0+3)*132 + e] = fmaxf(x3, 0.f);
        }
    }
    __syncthreads();

    // step B: m = relu(m1 @ W2 + b2), 8 rows x 4 packed col-pairs per thread
    int rg = tid >> 4, cg = tid & 15;
    const ulonglong2* W2v = (const ulonglong2*)(edge_w2v + (size_t)l*H*H);
    unsigned long long accp[8][4];
#pragma unroll
    for (int r = 0; r < 8; ++r)
#pragma unroll
        for (int c2 = 0; c2 < 4; ++c2) accp[r][c2] = 0ull;
#pragma unroll 4
    for (int k = 0; k < H; ++k) {
        float4 a0 = *(const float4*)(sm1 + k*132 + rg*8);
        float4 a1 = *(const float4*)(sm1 + k*132 + rg*8 + 4);
        ulonglong2 b0 = __ldg(W2v + k*32 + cg*2);
        ulonglong2 b1 = __ldg(W2v + k*32 + cg*2 + 1);
        unsigned long long bp[4] = {b0.x, b0.y, b1.x, b1.y};
        unsigned long long ad[8];
        ad[0] = dup2(a0.x); ad[1] = dup2(a0.y); ad[2] = dup2(a0.z); ad[3] = dup2(a0.w);
        ad[4] = dup2(a1.x); ad[5] = dup2(a1.y); ad[6] = dup2(a1.z); ad[7] = dup2(a1.w);
#pragma unroll
        for (int r = 0; r < 8; ++r)
#pragma unroll
            for (int c2 = 0; c2 < 4; ++c2) accp[r][c2] = fma2(ad[r], bp[c2], accp[r][c2]);
    }
    float acc[8][8];
#pragma unroll
    for (int r = 0; r < 8; ++r) {
#pragma unroll
        for (int c2 = 0; c2 < 4; ++c2) unpack2(accp[r][c2], acc[r][2*c2], acc[r][2*c2+1]);
#pragma unroll
        for (int c = 0; c < 8; ++c) acc[r][c] = fmaxf(acc[r][c] + sb2[cg*8+c], 0.f);
    }

    // step C: gate logits (reduce over feature dim via shared atomics)
#pragma unroll
    for (int r = 0; r < 8; ++r) {
        float p = 0.f;
#pragma unroll
        for (int c = 0; c < 8; ++c) p += acc[r][c]*sinfw[cg*8+c];
        atomicAdd(&sgate[rg*8 + r], p);
    }
    __syncthreads();
    if (tid < H) sgate[tid] = 1.f/(1.f + expf(-sgate[tid]));
    __syncthreads();

    // step D: mi[dst] = sum_e m*gate  (each thread's 8 rows live in one dst group)
    {
        int d = rg >> 2;
#pragma unroll
        for (int c = 0; c < 8; ++c) {
            float s = 0.f;
#pragma unroll
            for (int r = 0; r < 8; ++r) s += acc[r][c]*sgate[rg*8 + r];
            atomicAdd(&smi[d*H + cg*8 + c], s);
        }
    }
    __syncthreads();
    for (int i = tid; i < 4*H; i += 256) g_mi[(size_t)d0*H + i] = smi[i];
}

// ---------------- K6: node MLP + residual (packed f32x2) --------------------
__global__ void __launch_bounds__(256) node_kernel(const float* __restrict__ nw1,
                                                   const float* __restrict__ nb1,
                                                   const float* __restrict__ nw2,
                                                   const float* __restrict__ nb2, int l)
{
    __shared__ float sZ[256*34];   // [mi | h] k-major, then reused for u
    int tid = threadIdx.x;
    int nb = blockIdx.x*32;
    for (int i = tid; i < 32*H; i += 256) {
        int nn = i>>7, k = i&127;
        sZ[k*34 + nn]     = g_mi[(size_t)(nb+nn)*H + k];
        sZ[(H+k)*34 + nn] = g_h [(size_t)(nb+nn)*H + k];
    }
    __syncthreads();
    int cg = tid & 15, ng = tid >> 4, col = cg*8;
    const ulonglong2* W1a = (const ulonglong2*)(nw1 + (size_t)l*2*H*H);
    const ulonglong2* W1b = W1a + H*H/4;
    unsigned long long acc[2][4];
#pragma unroll
    for (int c2 = 0; c2 < 4; ++c2) {
        unsigned long long b = pack2(nb1[l*H + col + 2*c2], nb1[l*H + col + 2*c2 + 1]);
        acc[0][c2] = b; acc[1][c2] = b;
    }
#pragma unroll 4
    for (int k = 0; k < H; ++k) {
        float2 am = *(const float2*)(sZ + k*34 + ng*2);
        float2 ah = *(const float2*)(sZ + (H+k)*34 + ng*2);
        ulonglong2 wa0 = __ldg(W1a + k*32 + cg*2);
        ulonglong2 wa1 = __ldg(W1a + k*32 + cg*2 + 1);
        ulonglong2 wb0 = __ldg(W1b + k*32 + cg*2);
        ulonglong2 wb1 = __ldg(W1b + k*32 + cg*2 + 1);
        unsigned long long m0 = dup2(am.x), m1 = dup2(am.y);
        unsigned long long h0 = dup2(ah.x), h1 = dup2(ah.y);
        unsigned long long wap[4] = {wa0.x, wa0.y, wa1.x, wa1.y};
        unsigned long long wbp[4] = {wb0.x, wb0.y, wb1.x, wb1.y};
#pragma unroll
        for (int c2 = 0; c2 < 4; ++c2) {
            acc[0][c2] = fma2(m0, wap[c2], acc[0][c2]);
            acc[1][c2] = fma2(m1, wap[c2], acc[1][c2]);
            acc[0][c2] = fma2(h0, wbp[c2], acc[0][c2]);
            acc[1][c2] = fma2(h1, wbp[c2], acc[1][c2]);
        }
    }
    __syncthreads();   // done reading sZ
#pragma unroll
    for (int r = 0; r < 2; ++r)
#pragma unroll
        for (int c2 = 0; c2 < 4; ++c2) {
            float lo, hi;
            unpack2(acc[r][c2], lo, hi);
            sZ[(col + 2*c2)*34 + ng*2 + r]     = fmaxf(lo, 0.f);
            sZ[(col + 2*c2 + 1)*34 + ng*2 + r] = fmaxf(hi, 0.f);
        }
    __syncthreads();
    const ulonglong2* W2 = (const ulonglong2*)(nw2 + (size_t)l*H*H);
    unsigned long long acc2[2][4];
#pragma unroll
    for (int c2 = 0; c2 < 4; ++c2) {
        unsigned long long b = pack2(nb2[l*H + col + 2*c2], nb2[l*H + col + 2*c2 + 1]);
        acc2[0][c2] = b; acc2[1][c2] = b;
    }
#pragma unroll 4
    for (int k = 0; k < H; ++k) {
        float2 a  = *(const float2*)(sZ + k*34 + ng*2);
        ulonglong2 w0 = __ldg(W2 + k*32 + cg*2);
        ulonglong2 w1 = __ldg(W2 + k*32 + cg*2 + 1);
        unsigned long long a0 = dup2(a.x), a1 = dup2(a.y);
        unsigned long long wp[4] = {w0.x, w0.y, w1.x, w1.y};
#pragma unroll
        for (int c2 = 0; c2 < 4; ++c2) {
            acc2[0][c2] = fma2(a0, wp[c2], acc2[0][c2]);
            acc2[1][c2] = fma2(a1, wp[c2], acc2[1][c2]);
        }
    }
#pragma unroll
    for (int r = 0; r < 2; ++r) {
        float v[8];
#pragma unroll
        for (int c2 = 0; c2 < 4; ++c2) unpack2(acc2[r][c2], v[2*c2], v[2*c2+1]);
        size_t o = (size_t)(nb + ng*2 + r)*H + col;
        float4* hp = (float4*)(g_h + o);
        float4 h0 = hp[0], h1 = hp[1];
        h0.x += v[0]; h0.y += v[1]; h0.z += v[2]; h0.w += v[3];
        h1.x += v[4]; h1.y += v[5]; h1.z += v[6]; h1.w += v[7];
        hp[0] = h0; hp[1] = h1;
    }
}

// ---------------- K7: per-graph pooling (parallel + atomics) ----------------
__global__ void pool_kernel(int n)
{
    int b = blockIdx.x >> 4, s = blockIdx.x & 15;
    int c = threadIdx.x;  // 128 threads
    float acc = 0.f;
    for (int i = s; i < n; i += 16) acc += g_h[((size_t)b*n + i)*H + c];
    atomicAdd(&g_pre[b*H + c], acc);
}

// ---------------- K8: out_block + output selection ---------------------------
__global__ void out_kernel(const float* __restrict__ w1, const float* __restrict__ b1,
                           const float* __restrict__ w2, const float* __restrict__ b2,
                           const int* __restrict__ kind, float* __restrict__ out, int B)
{
    __shared__ float sU[H]; __shared__ float so[3];
    int t = threadIdx.x;
    for (int b = 0; b < B; ++b) {
        float x = b1[t];
        for (int k = 0; k < H; ++k) x += g_pre[b*H + k]*w1[k*H + t];
        float sp = (x > 0.f) ? x + log1pf(expf(-x)) : log1pf(expf(x));
        sU[t] = sp - 0.6931471805599453f;
        __syncthreads();
        if (t < 3) { float s = b2[t]; for (int k = 0; k < H; ++k) s += sU[k]*w2[k*3 + t]; so[t] = s; }
        __syncthreads();
        if (t == 0) out[b] = so[kind[b] - 1];
        __syncthreads();
    }
}

// ---------------- host ------------------------------------------------------
#define EDGE_SMEM ((128*132 + 20*128 + 128*20 + 4*128 + 128 + 128 + 128 + 4*128 + 128)*4)

extern "C" void kernel_launch(void* const* d_in, const int* in_sizes, int n_in,
                              void* d_out, int out_size)
{
    const float* protein_pos  = (const float*)d_in[0];
    const float* protein_feat = (const float*)d_in[1];
    const float* ligand_pos   = (const float*)d_in[2];
    const float* ligand_feat  = (const float*)d_in[3];
    const int*   output_kind  = (const int*)d_in[6];
    const float* prot_w = (const float*)d_in[7];  const float* prot_b = (const float*)d_in[8];
    const float* lig_w  = (const float*)d_in[9];  const float* lig_b  = (const float*)d_in[10];
    const float* edge_w1 = (const float*)d_in[11]; const float* edge_b1 = (const float*)d_in[12];
    const float* edge_w2 = (const float*)d_in[13]; const float* edge_b2 = (const float*)d_in[14];
    const float* inf_w   = (const float*)d_in[15]; const float* inf_b   = (const float*)d_in[16];
    const float* node_w1 = (const float*)d_in[17]; const float* node_b1 = (const float*)d_in[18];
    const float* node_w2 = (const float*)d_in[19]; const float* node_b2 = (const float*)d_in[20];
    const float* out_w1  = (const float*)d_in[21]; const float* out_b1  = (const float*)d_in[22];
    const float* out_w2  = (const float*)d_in[23]; const float* out_b2  = (const float*)d_in[24];
    float* out = (float*)d_out;

    int Np = in_sizes[0]/3, Nl = in_sizes[2]/3;
    int B  = in_sizes[6];
    int Fp = in_sizes[1]/Np, Fl = in_sizes[3]/Nl;
    int n_prot = Np/B, n_lig = Nl/B;
    int n = n_prot + n_lig;
    int N = Np + Nl;
    int E = N*KNN;

    cudaFuncSetAttribute(edge_kernel, cudaFuncAttributeMaxDynamicSharedMemorySize, EDGE_SMEM);

    embed_kernel<<<N, 128>>>(protein_pos, protein_feat, ligand_pos, ligand_feat,
                             prot_w, prot_b, lig_w, lig_b, n_prot, n_lig, n, Fp, Fl);

    knn_kernel<<<dim3((n + 127)/128, B), 128, n*3*sizeof(float)>>>(n);

    float step  = 10.0f/19.0f;           // CUTOFF / (G-1)
    float coeff = -0.5f/(step*step);
    attr_kernel<<<(E + 255)/256, 256>>>(E, step, coeff);

    ab_kernel<<<N/32, 256>>>(edge_w1, edge_b1, 0);
    for (int l = 0; l < 3; ++l) {
        edge_kernel<<<E/128, 256, EDGE_SMEM>>>(edge_w1, edge_b2, edge_w2, inf_w, inf_b, l);
        node_kernel<<<N/32, 256>>>(node_w1, node_b1, node_w2, node_b2, l);
        if (l < 2) ab_kernel<<<N/32, 256>>>(edge_w1, edge_b1, l + 1);
    }

    pool_kernel<<<B*16, 128>>>(n);
    out_kernel<<<1, 128>>>(out_w1, out_b1, out_w2, out_b2, output_kind, out, B);
}